// round 1
// baseline (speedup 1.0000x reference)
#include <cuda_runtime.h>
#include <cuda_bf16.h>

// 3x3 median blur, zero padding, on 48 planes of 512x512 fp32.
// Each thread computes 4 horizontal outputs:
//   - loads float4 + 2 boundary scalars per row (3 rows)
//   - sorts 6 columns of 3 (compare-exchange network)
//   - median9 = med3( max3(column mins), med3(column meds), min3(column maxs) )

#define CE(a, b) do { float _t = fminf(a, b); (b) = fmaxf(a, b); (a) = _t; } while (0)

__device__ __forceinline__ float med3f(float a, float b, float c) {
    // median of three without branches
    return fmaxf(fminf(a, b), fminf(fmaxf(a, b), c));
}

__global__ void __launch_bounds__(512) median3x3_kernel(
    const float* __restrict__ in, float* __restrict__ out)
{
    constexpr int W = 512;
    constexpr int H = 512;

    const int plane = blockIdx.y;                         // 0..47  (B*C)
    const int y     = blockIdx.x * blockDim.y + threadIdx.y; // 0..511
    const int x0    = threadIdx.x * 4;                    // 0..508, 16B aligned

    const float* p = in  + (size_t)plane * (H * W) + (size_t)y * W;
    float*       q = out + (size_t)plane * (H * W) + (size_t)y * W;

    // r[dy][i] : row y-1+dy, column x0-1+i  (i = 0..5)
    float r[3][6];
    #pragma unroll
    for (int dy = 0; dy < 3; dy++) {
        const int yy = y + dy - 1;
        if (yy < 0 || yy >= H) {
            #pragma unroll
            for (int i = 0; i < 6; i++) r[dy][i] = 0.0f;
        } else {
            const float* row = p + (dy - 1) * W;
            const float4 v = *reinterpret_cast<const float4*>(row + x0);
            r[dy][1] = v.x; r[dy][2] = v.y; r[dy][3] = v.z; r[dy][4] = v.w;
            r[dy][0] = (x0 > 0)     ? __ldg(row + x0 - 1) : 0.0f;
            r[dy][5] = (x0 + 4 < W) ? __ldg(row + x0 + 4) : 0.0f;
        }
    }

    // Sort each column of 3: lo <= mi <= hi
    float lo[6], mi[6], hi[6];
    #pragma unroll
    for (int i = 0; i < 6; i++) {
        float a = r[0][i], b = r[1][i], c = r[2][i];
        CE(a, b); CE(b, c); CE(a, b);
        lo[i] = a; mi[i] = b; hi[i] = c;
    }

    // 4 outputs from overlapping column triples
    float res[4];
    #pragma unroll
    for (int j = 0; j < 4; j++) {
        const float mx = fmaxf(fmaxf(lo[j], lo[j + 1]), lo[j + 2]);
        const float mn = fminf(fminf(hi[j], hi[j + 1]), hi[j + 2]);
        const float md = med3f(mi[j], mi[j + 1], mi[j + 2]);
        res[j] = med3f(mx, md, mn);
    }

    float4 o;
    o.x = res[0]; o.y = res[1]; o.z = res[2]; o.w = res[3];
    *reinterpret_cast<float4*>(q + x0) = o;
}

extern "C" void kernel_launch(void* const* d_in, const int* in_sizes, int n_in,
                              void* d_out, int out_size)
{
    const float* in  = (const float*)d_in[0];
    float*       out = (float*)d_out;

    // 48 planes (B*C) of 512x512. Block: 128 x-groups (4 px each) x 4 rows.
    dim3 block(128, 4, 1);
    dim3 grid(512 / 4, 48, 1);
    median3x3_kernel<<<grid, block>>>(in, out);
}